// round 2
// baseline (speedup 1.0000x reference)
#include <cuda_runtime.h>

// ROIAlign, torchvision semantics (matches the JAX reference):
//   features: (N=2, C=256, H=200, W=304) fp32, NCHW
//   boxes:    (R=1000, 5) fp32  [batch_idx, x1, y1, x2, y2] in image coords
//   output:   (R, C, 7, 7) fp32
// spatial_scale = 0.25, sampling_ratio = 2, mean over the 2x2 sample grid.

namespace {

constexpr int   C_DIM  = 256;
constexpr int   H_DIM  = 200;
constexpr int   W_DIM  = 304;
constexpr int   PH     = 7;
constexpr int   PW     = 7;
constexpr int   G      = 2;      // sampling_ratio
constexpr float SCALE  = 0.25f;

// torchvision bilinear_interpolate clamping along one axis.
__device__ __forceinline__ void axis_interp(float coord, int size,
                                            int& lo, int& hi,
                                            float& frac, bool& valid) {
    valid = (coord >= -1.0f) && (coord <= (float)size);
    float c = fmaxf(coord, 0.0f);
    int low = (int)c;                 // floor (c >= 0)
    if (low >= size - 1) {
        lo = size - 1; hi = size - 1; frac = 0.0f;
    } else {
        lo = low; hi = low + 1; frac = c - (float)low;
    }
}

__global__ void roi_align_kernel(const float* __restrict__ feat,
                                 const float* __restrict__ boxes,
                                 float* __restrict__ out,
                                 int total) {
    int idx = blockIdx.x * blockDim.x + threadIdx.x;
    if (idx >= total) return;

    // pw fastest -> warp covers spatial bins of one (box, channel) plane:
    // coalesced output writes, spatially-clustered feature gathers.
    int pw = idx % PW;
    int ph = (idx / PW) % PH;
    int c  = (idx / (PW * PH)) % C_DIM;
    int r  = idx / (PW * PH * C_DIM);

    const float* bx = boxes + (size_t)r * 5;
    int   b  = (int)__ldg(bx + 0);
    float x1 = __ldg(bx + 1) * SCALE;
    float y1 = __ldg(bx + 2) * SCALE;
    float x2 = __ldg(bx + 3) * SCALE;
    float y2 = __ldg(bx + 4) * SCALE;

    float roi_w = fmaxf(x2 - x1, 1.0f);
    float roi_h = fmaxf(y2 - y1, 1.0f);
    float bin_w = roi_w * (1.0f / PW);
    float bin_h = roi_h * (1.0f / PH);

    const float* fp = feat + ((size_t)b * C_DIM + c) * (H_DIM * W_DIM);

    // Per-axis sample interpolation params (shared across the 2x2 grid).
    int   yl[G], yh[G], xl[G], xh[G];
    float fy[G], fx[G];
    bool  vy[G], vx[G];
#pragma unroll
    for (int i = 0; i < G; i++) {
        float off = ((float)i + 0.5f) * (1.0f / G);
        float y = y1 + ((float)ph + off) * bin_h;
        float x = x1 + ((float)pw + off) * bin_w;
        axis_interp(y, H_DIM, yl[i], yh[i], fy[i], vy[i]);
        axis_interp(x, W_DIM, xl[i], xh[i], fx[i], vx[i]);
    }

    float acc = 0.0f;
#pragma unroll
    for (int iy = 0; iy < G; iy++) {
        if (!vy[iy]) continue;
        float ly = fy[iy], hy = 1.0f - ly;
        const float* rowl = fp + yl[iy] * W_DIM;
        const float* rowh = fp + yh[iy] * W_DIM;
#pragma unroll
        for (int ix = 0; ix < G; ix++) {
            if (!vx[ix]) continue;
            float lx = fx[ix], hx = 1.0f - lx;
            float vll = __ldg(rowl + xl[ix]);
            float vlh = __ldg(rowl + xh[ix]);
            float vhl = __ldg(rowh + xl[ix]);
            float vhh = __ldg(rowh + xh[ix]);
            acc += hy * (hx * vll + lx * vlh) + ly * (hx * vhl + lx * vhh);
        }
    }

    out[idx] = acc * (1.0f / (G * G));
}

} // namespace

extern "C" void kernel_launch(void* const* d_in, const int* in_sizes, int n_in,
                              void* d_out, int out_size) {
    const float* features = (const float*)d_in[0];
    const float* boxes    = (const float*)d_in[1];
    float*       out      = (float*)d_out;

    int total = out_size;            // R * C * PH * PW
    int threads = 256;
    int blocks = (total + threads - 1) / threads;
    roi_align_kernel<<<blocks, threads>>>(features, boxes, out, total);
}